// round 3
// baseline (speedup 1.0000x reference)
#include <cuda_runtime.h>
#include <math.h>

#define NB 64
#define NP 24564
#define NM 16
#define NC 21

// ---------------- scratch (device globals; no allocation allowed) ----------------
__device__ float              g_ov[NB * NP];     // best truth overlap per prior
__device__ int                g_tidx[NB * NP];   // best truth index per prior
__device__ float              g_mined[NB * NP];  // loss_c_mined (0 for pos)
__device__ unsigned long long g_bp[NB * NM];     // best prior key per truth
__device__ float              g_loss_l;
__device__ float              g_loss_c;
__device__ float              g_pos_conf[NB];
__device__ int                g_num_pos[NB];

// ---------------- init ----------------
__global__ void k_init() {
    int t = threadIdx.x;
    if (t < NB * NM) g_bp[t] = 0ull;
    if (t < NB) { g_pos_conf[t] = 0.f; g_num_pos[t] = 0; }
    if (t == 0) { g_loss_l = 0.f; g_loss_c = 0.f; }
}

// ---------------- match: per-prior best truth + per-truth best prior ----------------
__global__ void k_match(const float* __restrict__ priors,
                        const float* __restrict__ targets) {
    int b   = blockIdx.y;
    int tid = threadIdx.x;
    __shared__ float s_tr[NM][4];
    __shared__ float s_area[NM];
    __shared__ unsigned long long s_bp[NM][8];

    if (tid < NM * 4) {
        int m = tid >> 2, c = tid & 3;
        s_tr[m][c] = targets[(b * NM + m) * 5 + c];
    }
    __syncthreads();
    if (tid < NM)
        s_area[tid] = (s_tr[tid][2] - s_tr[tid][0]) * (s_tr[tid][3] - s_tr[tid][1]);
    __syncthreads();

    int p = blockIdx.x * blockDim.x + tid;
    float px1 = 0.f, py1 = 0.f, px2 = 0.f, py2 = 0.f, pa = 0.f;
    if (p < NP) {
        float4 pr = ((const float4*)priors)[p];
        px1 = pr.x - pr.z * 0.5f; py1 = pr.y - pr.w * 0.5f;
        px2 = pr.x + pr.z * 0.5f; py2 = pr.y + pr.w * 0.5f;
        pa  = (px2 - px1) * (py2 - py1);
    }

    float bestv = -1.f;
    int   bestj = 0;
    int lane = tid & 31, wp = tid >> 5;

    for (int j = 0; j < NM; j++) {
        float iw = fminf(s_tr[j][2], px2) - fmaxf(s_tr[j][0], px1);
        float ih = fminf(s_tr[j][3], py2) - fmaxf(s_tr[j][1], py1);
        iw = fmaxf(iw, 0.f); ih = fmaxf(ih, 0.f);
        float inter = iw * ih;
        float iou   = inter / (s_area[j] + pa - inter);
        if (p >= NP) iou = -1.f;
        if (iou > bestv) { bestv = iou; bestj = j; }  // strict > : first occurrence

        unsigned long long key = 0ull;
        if (p < NP)
            key = ((unsigned long long)__float_as_uint(iou) << 32)
                | (unsigned long long)(0xFFFFFFFFu - (unsigned)p);  // tie -> smaller p
        for (int off = 16; off; off >>= 1) {
            unsigned long long o = __shfl_down_sync(0xFFFFFFFFu, key, off);
            if (o > key) key = o;
        }
        if (lane == 0) s_bp[j][wp] = key;
    }

    if (p < NP) {
        g_ov[b * NP + p]   = bestv;
        g_tidx[b * NP + p] = bestj;
    }
    __syncthreads();
    if (tid < NM) {
        unsigned long long best = 0ull;
        #pragma unroll
        for (int w = 0; w < 8; w++) {
            unsigned long long v = s_bp[tid][w];
            if (v > best) best = v;
        }
        atomicMax(&g_bp[b * NM + tid], best);
    }
}

// ---------------- override: force each truth's best prior (last-wins on dup) ----------------
__global__ void k_override() {
    int b = threadIdx.x;
    if (b < NB) {
        for (int j = 0; j < NM; j++) {
            unsigned long long key = g_bp[b * NM + j];
            unsigned p = 0xFFFFFFFFu - (unsigned)(key & 0xFFFFFFFFull);
            g_ov[b * NP + p]   = 2.0f;
            g_tidx[b * NP + p] = j;
        }
    }
}

// ---------------- per-prior losses (HBM-bound heavy pass) ----------------
__global__ void k_loss(const float* __restrict__ loc,
                       const float* __restrict__ conf,
                       const float* __restrict__ priors,
                       const float* __restrict__ targets) {
    int b   = blockIdx.y;
    int tid = threadIdx.x;
    int p0  = blockIdx.x * 256;
    __shared__ float s_conf[256 * NC];
    __shared__ float s_tr[NM][5];
    __shared__ float r_ll[8], r_pc[8];
    __shared__ int   r_np[8];

    int nvalid = NP - p0; if (nvalid > 256) nvalid = 256;
    // conf row block start: (b*NP+p0)*21 floats. b*NP*84B and p0*84B (p0 mult of 256)
    // are both 16B-aligned; nvalid*21 is divisible by 4 for every block -> pure float4.
    const float4* src4 = (const float4*)(conf + ((size_t)b * NP + p0) * NC);
    float4*       dst4 = (float4*)s_conf;
    int n4 = (nvalid * NC) >> 2;
    for (int i = tid; i < n4; i += 256) dst4[i] = src4[i];
    if (tid < NM * 5) s_tr[tid / 5][tid % 5] = targets[b * NM * 5 + tid];
    __syncthreads();

    int p = p0 + tid;
    float my_ll = 0.f, my_pc = 0.f;
    int   my_np = 0;

    if (p < NP) {
        float ov  = g_ov[b * NP + p];
        int   j   = g_tidx[b * NP + p];
        bool  pos = (ov >= 0.5f);                     // labels>=0 so conf>=1 when kept
        int   ct  = pos ? ((int)s_tr[j][4] + 1) : 0;

        const float* cr = &s_conf[tid * NC];
        float mx = cr[0];
        #pragma unroll
        for (int c = 1; c < NC; c++) mx = fmaxf(mx, cr[c]);
        float s = 0.f;
        #pragma unroll
        for (int c = 0; c < NC; c++) s += expf(cr[c] - mx);
        float lse = mx + logf(s);
        float lca = lse - cr[ct];

        g_mined[b * NP + p] = pos ? 0.f : lca;

        if (pos) {
            my_pc = lca;
            my_np = 1;
            float4 pr = ((const float4*)priors)[p];
            float4 ld = ((const float4*)loc)[(size_t)b * NP + p];
            float tx1 = s_tr[j][0], ty1 = s_tr[j][1];
            float tx2 = s_tr[j][2], ty2 = s_tr[j][3];
            float gx = ((tx1 + tx2) * 0.5f - pr.x) / (0.1f * pr.z);
            float gy = ((ty1 + ty2) * 0.5f - pr.y) / (0.1f * pr.w);
            float gw = logf((tx2 - tx1) / pr.z) / 0.2f;
            float gh = logf((ty2 - ty1) / pr.w) / 0.2f;
            float d, a;
            d = ld.x - gx; a = fabsf(d); my_ll += (a < 1.f) ? (0.5f * d * d) : (a - 0.5f);
            d = ld.y - gy; a = fabsf(d); my_ll += (a < 1.f) ? (0.5f * d * d) : (a - 0.5f);
            d = ld.z - gw; a = fabsf(d); my_ll += (a < 1.f) ? (0.5f * d * d) : (a - 0.5f);
            d = ld.w - gh; a = fabsf(d); my_ll += (a < 1.f) ? (0.5f * d * d) : (a - 0.5f);
        }
    }

    // block reduce
    int lane = tid & 31, wp = tid >> 5;
    for (int off = 16; off; off >>= 1) {
        my_ll += __shfl_down_sync(0xFFFFFFFFu, my_ll, off);
        my_pc += __shfl_down_sync(0xFFFFFFFFu, my_pc, off);
        my_np += __shfl_down_sync(0xFFFFFFFFu, my_np, off);
    }
    if (lane == 0) { r_ll[wp] = my_ll; r_pc[wp] = my_pc; r_np[wp] = my_np; }
    __syncthreads();
    if (tid == 0) {
        float tll = 0.f, tpc = 0.f; int tnp = 0;
        #pragma unroll
        for (int w = 0; w < 8; w++) { tll += r_ll[w]; tpc += r_pc[w]; tnp += r_np[w]; }
        atomicAdd(&g_loss_l, tll);
        atomicAdd(&g_pos_conf[b], tpc);
        atomicAdd(&g_num_pos[b], tnp);
    }
}

// ---------------- hard-negative mining: radix top-k SUM per batch ----------------
// Sum of top-num_neg mined values == neg contribution to loss_c (pos have mined=0).
__global__ void k_select() {
    int b   = blockIdx.x;
    int tid = threadIdx.x;
    __shared__ int      bins[256];
    __shared__ unsigned s_pref;
    __shared__ int      s_krem;
    __shared__ float    r_s[8];

    const float* data = &g_mined[b * NP];

    if (tid == 0) {
        s_pref = 0u;
        long long kk = 3LL * (long long)g_num_pos[b];
        if (kk > NP - 1) kk = NP - 1;
        s_krem = (int)kk;          // >= 3 (forced matches guarantee num_pos >= 1)
    }
    __syncthreads();

    for (int byte = 3; byte >= 0; --byte) {
        unsigned pref = s_pref;
        bins[tid] = 0;
        __syncthreads();
        int shift = byte * 8;
        for (int i = tid; i < NP; i += 256) {
            unsigned u = __float_as_uint(data[i]);   // all values >= 0 -> bits monotone
            bool ok = (byte == 3) || ((u >> (shift + 8)) == pref);
            if (ok) atomicAdd(&bins[(u >> shift) & 255], 1);
        }
        __syncthreads();
        if (tid == 0) {
            int krem = s_krem, cum = 0, sel = 0;
            for (int t = 255; t >= 0; --t) {
                int c = bins[t];
                if (cum + c >= krem) { sel = t; break; }
                cum += c;
            }
            s_krem = krem - cum;
            s_pref = (pref << 8) | (unsigned)sel;
        }
        __syncthreads();
    }

    unsigned thr  = s_pref;
    int      krem = s_krem;
    float s = 0.f;
    for (int i = tid; i < NP; i += 256) {
        unsigned u = __float_as_uint(data[i]);
        if (u > thr) s += data[i];
    }
    int lane = tid & 31, wp = tid >> 5;
    for (int off = 16; off; off >>= 1) s += __shfl_down_sync(0xFFFFFFFFu, s, off);
    if (lane == 0) r_s[wp] = s;
    __syncthreads();
    if (tid == 0) {
        float tot = 0.f;
        #pragma unroll
        for (int w = 0; w < 8; w++) tot += r_s[w];
        tot += (float)krem * __uint_as_float(thr);   // boundary-tied elements
        tot += g_pos_conf[b];                        // pos contribution (union pos|neg)
        atomicAdd(&g_loss_c, tot);
    }
}

// ---------------- finalize ----------------
__global__ void k_final(float* __restrict__ out) {
    int n = 0;
    for (int b = 0; b < NB; b++) n += g_num_pos[b];
    float fn = (float)n;
    out[0] = g_loss_l / fn;
    out[1] = g_loss_c / fn;
}

// ---------------- launch ----------------
extern "C" void kernel_launch(void* const* d_in, const int* in_sizes, int n_in,
                              void* d_out, int out_size) {
    const float* loc     = (const float*)d_in[0];
    const float* conf    = (const float*)d_in[1];
    const float* priors  = (const float*)d_in[2];
    const float* targets = (const float*)d_in[3];
    float*       out     = (float*)d_out;

    dim3 grid((NP + 255) / 256, NB);
    k_init<<<1, 1024>>>();
    k_match<<<grid, 256>>>(priors, targets);
    k_override<<<1, 64>>>();
    k_loss<<<grid, 256>>>(loc, conf, priors, targets);
    k_select<<<NB, 256>>>();
    k_final<<<1, 1>>>(out);
}